// round 7
// baseline (speedup 1.0000x reference)
#include <cuda_runtime.h>
#include <cuda_bf16.h>
#include <cstdint>

#define DF 1024
#define NH 16
#define DH 64
#define BB 2
#define SS 2048
#define MROWS (BB*SS)

#define KW   3072              // split-K width (3 * 1024)
#define KC   64                // bf16 K per SMEM chunk
#define NCHUNK (KW / KC)       // 48
#define NSTAGE 3
#define PITCH  72              // bf16 elems per smem row (64 + 8 pad) = 144B
#define PITCHB 144
#define OP_BYTES (128 * PITCHB)             // 18432
#define STAGE_BYTES (2 * OP_BYTES)          // 36864
#define GEMM_SMEM (512 + NSTAGE * STAGE_BYTES)  // 111104

// attention smem
#define ATILE   9216                       // one 64x64 bf16 tile, pitch 144
#define ASTRIDE (4 * ATILE + 256)          // Kh,Kl,Vh,Vl + mask = 37120
#define QL_OFF  18432
#define ATTN_SMEM (3 * ASTRIDE)            // 111360

// ---------------------------------------------------------------------------
// Scratch
// ---------------------------------------------------------------------------
__device__ __nv_bfloat16 g_A3[(size_t)MROWS * KW];   // activations, split [hi|lo|hi]
__device__ __nv_bfloat16 g_W3[(size_t)DF * KW];      // weights,     split [hi|hi|lo]
__device__ __nv_bfloat16 g_Qh[(size_t)BB * NH * SS * DH];
__device__ __nv_bfloat16 g_Ql[(size_t)BB * NH * SS * DH];
__device__ __nv_bfloat16 g_Kh[(size_t)BB * NH * SS * DH];
__device__ __nv_bfloat16 g_Kl[(size_t)BB * NH * SS * DH];
__device__ __nv_bfloat16 g_Vh[(size_t)BB * NH * SS * DH];
__device__ __nv_bfloat16 g_Vl[(size_t)BB * NH * SS * DH];

// ---------------------------------------------------------------------------
// helpers
// ---------------------------------------------------------------------------
__device__ __forceinline__ uint32_t smem_u32(const void* p) {
    uint32_t a;
    asm("{ .reg .u64 t; cvta.to.shared.u64 t, %1; cvt.u32.u64 %0, t; }"
        : "=r"(a) : "l"(p));
    return a;
}

__device__ __forceinline__ void cp_async_16(uint32_t dst, const void* src) {
    asm volatile("cp.async.cg.shared.global [%0], [%1], 16;" :: "r"(dst), "l"(src) : "memory");
}
#define CP_COMMIT() asm volatile("cp.async.commit_group;" ::: "memory")
#define CP_WAIT1()  asm volatile("cp.async.wait_group 1;" ::: "memory")
#define CP_WAIT0()  asm volatile("cp.async.wait_group 0;" ::: "memory")

__device__ __forceinline__ void ldsm_x4(uint32_t& r0, uint32_t& r1, uint32_t& r2,
                                        uint32_t& r3, uint32_t addr) {
    asm volatile("ldmatrix.sync.aligned.m8n8.x4.shared.b16 {%0,%1,%2,%3}, [%4];"
                 : "=r"(r0), "=r"(r1), "=r"(r2), "=r"(r3) : "r"(addr));
}
__device__ __forceinline__ void ldsm_x4_t(uint32_t& r0, uint32_t& r1, uint32_t& r2,
                                          uint32_t& r3, uint32_t addr) {
    asm volatile("ldmatrix.sync.aligned.m8n8.x4.trans.shared.b16 {%0,%1,%2,%3}, [%4];"
                 : "=r"(r0), "=r"(r1), "=r"(r2), "=r"(r3) : "r"(addr));
}

__device__ __forceinline__ void mma16816(float* d, const uint32_t* a, const uint32_t* b) {
    asm volatile(
        "mma.sync.aligned.m16n8k16.row.col.f32.bf16.bf16.f32 "
        "{%0,%1,%2,%3}, {%4,%5,%6,%7}, {%8,%9}, {%0,%1,%2,%3};"
        : "+f"(d[0]), "+f"(d[1]), "+f"(d[2]), "+f"(d[3])
        : "r"(a[0]), "r"(a[1]), "r"(a[2]), "r"(a[3]), "r"(b[0]), "r"(b[1]));
}

// truncation hi-split + rounded lo-split of a float pair into two bf16x2 words
__device__ __forceinline__ void split_pack(float x, float y, uint32_t& hp, uint32_t& lp) {
    uint32_t ux = __float_as_uint(x), uy = __float_as_uint(y);
    hp = __byte_perm(ux, uy, 0x7632);
    float lx = x - __uint_as_float(ux & 0xffff0000u);
    float ly = y - __uint_as_float(uy & 0xffff0000u);
    __nv_bfloat162 l2 = __floats2bfloat162_rn(lx, ly);
    lp = *reinterpret_cast<uint32_t*>(&l2);
}

// ---------------------------------------------------------------------------
// Split-bf16 conversion (inputs -> A3 / weights -> W3)
//   mode 0 (activations): [0:1024]=hi  [1024:2048]=lo  [2048:3072]=hi
//   mode 1 (weights):     [0:1024]=hi  [1024:2048]=hi  [2048:3072]=lo
// ---------------------------------------------------------------------------
template<int MODE>
__global__ __launch_bounds__(256) void conv_split(const float* __restrict__ X,
                                                  __nv_bfloat16* __restrict__ Y)
{
    int idx = (blockIdx.x * 256 + threadIdx.x) * 4;
    float4 x = *reinterpret_cast<const float4*>(X + idx);
    float v[4] = {x.x, x.y, x.z, x.w};
    __nv_bfloat16 hi[4], lo[4];
    #pragma unroll
    for (int i = 0; i < 4; i++) {
        hi[i] = __float2bfloat16(v[i]);
        lo[i] = __float2bfloat16(v[i] - __bfloat162float(hi[i]));
    }
    uint64_t hip, lop;
    memcpy(&hip, hi, 8);
    memcpy(&lop, lo, 8);
    int r = idx >> 10, k = idx & 1023;
    size_t base = (size_t)r * KW + k;
    uint64_t* y0 = reinterpret_cast<uint64_t*>(Y + base);
    uint64_t* y1 = reinterpret_cast<uint64_t*>(Y + base + 1024);
    uint64_t* y2 = reinterpret_cast<uint64_t*>(Y + base + 2048);
    *y0 = hip;
    if (MODE == 0) { *y1 = lop; *y2 = hip; }
    else           { *y1 = hip; *y2 = lop; }
}

// ---------------------------------------------------------------------------
// mma.sync GEMM: C[4096,1024] = A3 @ W3^T + bias
// EPI=0: write fp32 to C.   EPI=1: write split bf16 head-major to (H, L).
// ---------------------------------------------------------------------------
template<int EPI>
__global__ void __launch_bounds__(256, 1)
gemm_mma(const __nv_bfloat16* __restrict__ A3, const __nv_bfloat16* __restrict__ W3,
         const float* __restrict__ bias, float* __restrict__ C,
         __nv_bfloat16* __restrict__ H, __nv_bfloat16* __restrict__ L)
{
    extern __shared__ char smem[];
    const uint32_t sb = smem_u32(smem);
    const int tid = threadIdx.x;
    const int wid = tid >> 5, lid = tid & 31;
    const int m0 = blockIdx.y * 128;
    const int n0 = blockIdx.x * 128;

    float* bias_s = (float*)smem;
    if (tid < 128) bias_s[tid] = bias[n0 + tid];

    const __nv_bfloat16* Abase = A3 + (size_t)m0 * KW;
    const __nv_bfloat16* Wbase = W3 + (size_t)n0 * KW;

    auto load_chunk = [&](int c, int s) {
        const int k0 = c * KC;
        const uint32_t stage = sb + 512 + s * STAGE_BYTES;
        #pragma unroll
        for (int i = 0; i < 8; i++) {
            int seg = i * 256 + tid;
            int op  = seg >> 10;
            int r   = (seg & 1023) >> 3;
            int cs  = seg & 7;
            uint32_t dst = stage + op * OP_BYTES + (uint32_t)(r * PITCHB + cs * 16);
            const __nv_bfloat16* src = (op == 0 ? Abase : Wbase)
                                       + (size_t)r * KW + k0 + cs * 8;
            cp_async_16(dst, src);
        }
    };

    const int m0w = (wid & 3) * 32;
    const int n0w = (wid >> 2) * 64;

    float acc[2][8][4];
    #pragma unroll
    for (int mi = 0; mi < 2; mi++)
        #pragma unroll
        for (int nj = 0; nj < 8; nj++)
            #pragma unroll
            for (int e = 0; e < 4; e++) acc[mi][nj][e] = 0.f;

    load_chunk(0, 0); CP_COMMIT();
    load_chunk(1, 1); CP_COMMIT();

    for (int c = 0; c < NCHUNK; c++) {
        const int s = c % NSTAGE;
        CP_WAIT1();
        __syncthreads();

        int cn = c + 2;
        if (cn < NCHUNK) load_chunk(cn, cn % NSTAGE);
        CP_COMMIT();

        const uint32_t sA = sb + 512 + s * STAGE_BYTES;
        const uint32_t sW = sA + OP_BYTES;

        #pragma unroll
        for (int kk = 0; kk < 4; kk++) {
            uint32_t a[2][4];
            #pragma unroll
            for (int mi = 0; mi < 2; mi++) {
                uint32_t addr = sA + (uint32_t)((m0w + mi * 16 + (lid & 15)) * PITCHB
                                 + kk * 32 + ((lid >> 4) << 4));
                ldsm_x4(a[mi][0], a[mi][1], a[mi][2], a[mi][3], addr);
            }
            uint32_t b[8][2];
            #pragma unroll
            for (int ni = 0; ni < 4; ni++) {
                uint32_t addr = sW + (uint32_t)((n0w + ni * 16 + (lid & 7)
                                 + ((lid >> 4) & 1) * 8) * PITCHB
                                 + kk * 32 + (((lid >> 3) & 1) << 4));
                uint32_t r0, r1, r2, r3;
                ldsm_x4(r0, r1, r2, r3, addr);
                b[2 * ni][0] = r0; b[2 * ni][1] = r1;
                b[2 * ni + 1][0] = r2; b[2 * ni + 1][1] = r3;
            }
            #pragma unroll
            for (int mi = 0; mi < 2; mi++)
                #pragma unroll
                for (int nj = 0; nj < 8; nj++)
                    mma16816(acc[mi][nj], a[mi], b[nj]);
        }
        __syncthreads();
    }
    CP_WAIT0();

    const int g = lid >> 2, t = lid & 3;
    #pragma unroll
    for (int mi = 0; mi < 2; mi++) {
        #pragma unroll
        for (int nj = 0; nj < 8; nj++) {
            int colrel = n0w + nj * 8 + 2 * t;
            int col = n0 + colrel;
            int row0 = m0 + m0w + mi * 16 + g;
            float c0 = acc[mi][nj][0] + bias_s[colrel];
            float c1 = acc[mi][nj][1] + bias_s[colrel + 1];
            float c2 = acc[mi][nj][2] + bias_s[colrel];
            float c3 = acc[mi][nj][3] + bias_s[colrel + 1];
            if (EPI == 0) {
                float2 v0 = {c0, c1}, v1 = {c2, c3};
                *reinterpret_cast<float2*>(C + (size_t)row0 * DF + col) = v0;
                *reinterpret_cast<float2*>(C + (size_t)(row0 + 8) * DF + col) = v1;
            } else {
                int bb_ = row0 >> 11, sidx = row0 & 2047;
                int hh  = col >> 6,   dh   = col & 63;
                size_t dst = ((size_t)(bb_ * NH + hh) * SS + sidx) * DH + dh;
                uint32_t hp, lp;
                split_pack(c0, c1, hp, lp);
                *reinterpret_cast<uint32_t*>(H + dst) = hp;
                *reinterpret_cast<uint32_t*>(L + dst) = lp;
                split_pack(c2, c3, hp, lp);
                *reinterpret_cast<uint32_t*>(H + dst + 8 * DH) = hp;
                *reinterpret_cast<uint32_t*>(L + dst + 8 * DH) = lp;
            }
        }
    }
}

// ---------------------------------------------------------------------------
// FlashAttention-2 on mma.sync, 3-term bf16 split for QK^T and PV.
// CTA: 128 queries x one (b,h). 8 warps x 16 rows. 64-key tiles, 3-stage pipe.
// Writes normalized output directly into A3 split layout [hi|lo|hi].
// ---------------------------------------------------------------------------
__global__ void __launch_bounds__(256, 1)
attn_mma(const __nv_bfloat16* __restrict__ Qh_, const __nv_bfloat16* __restrict__ Ql_,
         const __nv_bfloat16* __restrict__ Kh_, const __nv_bfloat16* __restrict__ Kl_,
         const __nv_bfloat16* __restrict__ Vh_, const __nv_bfloat16* __restrict__ Vl_,
         const int* __restrict__ mask, __nv_bfloat16* __restrict__ A3out)
{
    extern __shared__ char smem[];
    const uint32_t sb = smem_u32(smem);
    const int tid = threadIdx.x, wid = tid >> 5, lid = tid & 31;
    const int g = lid >> 2, t4 = lid & 3;
    const int b = blockIdx.z, h = blockIdx.y;
    const int bh = b * NH + h;
    const int q0 = blockIdx.x * 128;
    const int m0w = wid * 16;
    const float SC = 0.03125f;   // 1/sqrt(D_FEAT) = 1/32

    // ---- stage Q (hi,lo) through smem into register a-frags ----
    {
        const size_t qbase = ((size_t)bh * SS + q0);
        #pragma unroll
        for (int i = 0; i < 4; i++) {
            int seg = i * 256 + tid;             // 0..1023
            int row = seg >> 3, cs = seg & 7;
            const size_t src = (qbase + row) * DH + cs * 8;
            uint32_t d = sb + (uint32_t)(row * PITCHB + cs * 16);
            cp_async_16(d,          Qh_ + src);
            cp_async_16(d + QL_OFF, Ql_ + src);
        }
    }
    CP_COMMIT(); CP_WAIT0(); __syncthreads();

    uint32_t qh[4][4], ql[4][4];
    #pragma unroll
    for (int kk = 0; kk < 4; kk++) {
        uint32_t a = sb + (uint32_t)((m0w + (lid & 15)) * PITCHB + kk * 32 + ((lid >> 4) << 4));
        ldsm_x4(qh[kk][0], qh[kk][1], qh[kk][2], qh[kk][3], a);
        ldsm_x4(ql[kk][0], ql[kk][1], ql[kk][2], ql[kk][3], a + QL_OFF);
    }
    __syncthreads();

    auto load_tile = [&](int ti, int st) {
        const uint32_t stage = sb + st * ASTRIDE;
        const size_t kbase = ((size_t)bh * SS + ti * 64);
        #pragma unroll
        for (int i = 0; i < 2; i++) {
            int seg = i * 256 + tid;             // 0..511
            int row = seg >> 3, cs = seg & 7;
            size_t src = (kbase + row) * DH + cs * 8;
            uint32_t d = stage + (uint32_t)(row * PITCHB + cs * 16);
            cp_async_16(d,             Kh_ + src);
            cp_async_16(d + ATILE,     Kl_ + src);
            cp_async_16(d + 2 * ATILE, Vh_ + src);
            cp_async_16(d + 3 * ATILE, Vl_ + src);
        }
        if (tid < 16)
            cp_async_16(stage + 4 * ATILE + tid * 16, mask + b * SS + ti * 64 + tid * 4);
    };

    float m0 = -1e30f, m1 = -1e30f, l0 = 0.f, l1 = 0.f;
    float o[8][4];
    #pragma unroll
    for (int nj = 0; nj < 8; nj++)
        #pragma unroll
        for (int e = 0; e < 4; e++) o[nj][e] = 0.f;

    load_tile(0, 0); CP_COMMIT();
    load_tile(1, 1); CP_COMMIT();

    for (int ti = 0; ti < SS / 64; ti++) {
        const int st = ti % 3;
        CP_WAIT1();
        __syncthreads();
        if (ti + 2 < SS / 64) load_tile(ti + 2, (ti + 2) % 3);
        CP_COMMIT();

        const uint32_t sK  = sb + st * ASTRIDE;
        const uint32_t sKl = sK + ATILE, sV = sK + 2 * ATILE, sVl = sK + 3 * ATILE;
        const int* mk = (const int*)(smem + st * ASTRIDE + 4 * ATILE);

        // ---- S = Qh Kh^T + Ql Kh^T + Qh Kl^T ----
        float s[8][4];
        #pragma unroll
        for (int nj = 0; nj < 8; nj++)
            #pragma unroll
            for (int e = 0; e < 4; e++) s[nj][e] = 0.f;

        #pragma unroll
        for (int kk = 0; kk < 4; kk++) {
            uint32_t kb[4][4];
            #pragma unroll
            for (int ni = 0; ni < 4; ni++) {
                uint32_t a = sK + (uint32_t)((ni * 16 + (lid & 7) + ((lid >> 4) & 1) * 8) * PITCHB
                             + kk * 32 + (((lid >> 3) & 1) << 4));
                ldsm_x4(kb[ni][0], kb[ni][1], kb[ni][2], kb[ni][3], a);
            }
            #pragma unroll
            for (int nj = 0; nj < 8; nj++) mma16816(s[nj], qh[kk], &kb[nj >> 1][(nj & 1) * 2]);
            #pragma unroll
            for (int nj = 0; nj < 8; nj++) mma16816(s[nj], ql[kk], &kb[nj >> 1][(nj & 1) * 2]);
            #pragma unroll
            for (int ni = 0; ni < 4; ni++) {
                uint32_t a = sKl + (uint32_t)((ni * 16 + (lid & 7) + ((lid >> 4) & 1) * 8) * PITCHB
                             + kk * 32 + (((lid >> 3) & 1) << 4));
                ldsm_x4(kb[ni][0], kb[ni][1], kb[ni][2], kb[ni][3], a);
            }
            #pragma unroll
            for (int nj = 0; nj < 8; nj++) mma16816(s[nj], qh[kk], &kb[nj >> 1][(nj & 1) * 2]);
        }

        // ---- scale + mask + online softmax ----
        float tmax0 = -1e30f, tmax1 = -1e30f;
        #pragma unroll
        for (int nj = 0; nj < 8; nj++) {
            int c0 = nj * 8 + 2 * t4;
            int mk0 = mk[c0], mk1 = mk[c0 + 1];
            float s0 = s[nj][0] * SC; if (mk0 == 0) s0 = -1e9f;
            float s1 = s[nj][1] * SC; if (mk1 == 0) s1 = -1e9f;
            float s2 = s[nj][2] * SC; if (mk0 == 0) s2 = -1e9f;
            float s3 = s[nj][3] * SC; if (mk1 == 0) s3 = -1e9f;
            s[nj][0] = s0; s[nj][1] = s1; s[nj][2] = s2; s[nj][3] = s3;
            tmax0 = fmaxf(tmax0, fmaxf(s0, s1));
            tmax1 = fmaxf(tmax1, fmaxf(s2, s3));
        }
        tmax0 = fmaxf(tmax0, __shfl_xor_sync(0xffffffffu, tmax0, 1));
        tmax0 = fmaxf(tmax0, __shfl_xor_sync(0xffffffffu, tmax0, 2));
        tmax1 = fmaxf(tmax1, __shfl_xor_sync(0xffffffffu, tmax1, 1));
        tmax1 = fmaxf(tmax1, __shfl_xor_sync(0xffffffffu, tmax1, 2));

        float mn0 = fmaxf(m0, tmax0), mn1 = fmaxf(m1, tmax1);
        float sc0 = __expf(m0 - mn0), sc1 = __expf(m1 - mn1);
        m0 = mn0; m1 = mn1;
        l0 *= sc0; l1 *= sc1;
        #pragma unroll
        for (int nj = 0; nj < 8; nj++) {
            o[nj][0] *= sc0; o[nj][1] *= sc0;
            o[nj][2] *= sc1; o[nj][3] *= sc1;
        }
        #pragma unroll
        for (int nj = 0; nj < 8; nj++) {
            float p0 = __expf(s[nj][0] - m0);
            float p1 = __expf(s[nj][1] - m0);
            float p2 = __expf(s[nj][2] - m1);
            float p3 = __expf(s[nj][3] - m1);
            s[nj][0] = p0; s[nj][1] = p1; s[nj][2] = p2; s[nj][3] = p3;
            l0 += p0 + p1; l1 += p2 + p3;
        }

        // ---- O += Ph Vh + Pl Vh + Ph Vl ----
        #pragma unroll
        for (int kk = 0; kk < 4; kk++) {
            uint32_t ah[4], al[4];
            split_pack(s[2 * kk][0],     s[2 * kk][1],     ah[0], al[0]);
            split_pack(s[2 * kk][2],     s[2 * kk][3],     ah[1], al[1]);
            split_pack(s[2 * kk + 1][0], s[2 * kk + 1][1], ah[2], al[2]);
            split_pack(s[2 * kk + 1][2], s[2 * kk + 1][3], ah[3], al[3]);

            uint32_t vb[4][4];
            #pragma unroll
            for (int njp = 0; njp < 4; njp++) {
                uint32_t a = sV + (uint32_t)((16 * kk + (lid & 7) + ((lid >> 3) & 1) * 8) * PITCHB
                             + (16 * njp + ((lid >> 4) & 1) * 8) * 2);
                ldsm_x4_t(vb[njp][0], vb[njp][1], vb[njp][2], vb[njp][3], a);
            }
            #pragma unroll
            for (int nj = 0; nj < 8; nj++) mma16816(o[nj], ah, &vb[nj >> 1][(nj & 1) * 2]);
            #pragma unroll
            for (int nj = 0; nj < 8; nj++) mma16816(o[nj], al, &vb[nj >> 1][(nj & 1) * 2]);
            #pragma unroll
            for (int njp = 0; njp < 4; njp++) {
                uint32_t a = sVl + (uint32_t)((16 * kk + (lid & 7) + ((lid >> 3) & 1) * 8) * PITCHB
                             + (16 * njp + ((lid >> 4) & 1) * 8) * 2);
                ldsm_x4_t(vb[njp][0], vb[njp][1], vb[njp][2], vb[njp][3], a);
            }
            #pragma unroll
            for (int nj = 0; nj < 8; nj++) mma16816(o[nj], ah, &vb[nj >> 1][(nj & 1) * 2]);
        }
        __syncthreads();
    }
    CP_WAIT0();

    // ---- finalize + write split bf16 straight into A3 [hi|lo|hi] ----
    l0 += __shfl_xor_sync(0xffffffffu, l0, 1);
    l0 += __shfl_xor_sync(0xffffffffu, l0, 2);
    l1 += __shfl_xor_sync(0xffffffffu, l1, 1);
    l1 += __shfl_xor_sync(0xffffffffu, l1, 2);
    float inv0 = 1.f / l0, inv1 = 1.f / l1;

    const int srow = q0 + m0w + g;
    size_t r0 = (size_t)(b * SS + srow) * KW;
    size_t r1 = r0 + (size_t)8 * KW;
    const int colbase = h * DH;

    #pragma unroll
    for (int nj = 0; nj < 8; nj++) {
        int c = colbase + nj * 8 + 2 * t4;
        uint32_t hp, lp;
        split_pack(o[nj][0] * inv0, o[nj][1] * inv0, hp, lp);
        *reinterpret_cast<uint32_t*>(A3out + r0 + c)        = hp;
        *reinterpret_cast<uint32_t*>(A3out + r0 + 1024 + c) = lp;
        *reinterpret_cast<uint32_t*>(A3out + r0 + 2048 + c) = hp;
        split_pack(o[nj][2] * inv1, o[nj][3] * inv1, hp, lp);
        *reinterpret_cast<uint32_t*>(A3out + r1 + c)        = hp;
        *reinterpret_cast<uint32_t*>(A3out + r1 + 1024 + c) = lp;
        *reinterpret_cast<uint32_t*>(A3out + r1 + 2048 + c) = hp;
    }
}

// ---------------------------------------------------------------------------
// launch
// ---------------------------------------------------------------------------
extern "C" void kernel_launch(void* const* d_in, const int* in_sizes, int n_in,
                              void* d_out, int out_size)
{
    const float* Q    = (const float*)d_in[0];
    const float* K    = (const float*)d_in[1];
    const float* V    = (const float*)d_in[2];
    const int*   mask = (const int*)  d_in[3];
    const float* Wq   = (const float*)d_in[4];
    const float* bq   = (const float*)d_in[5];
    const float* Wk   = (const float*)d_in[6];
    const float* bk   = (const float*)d_in[7];
    const float* Wv   = (const float*)d_in[8];
    const float* bv   = (const float*)d_in[9];
    const float* Wo   = (const float*)d_in[10];
    const float* bo   = (const float*)d_in[11];
    float* out = (float*)d_out;

    __nv_bfloat16 *A3, *W3, *Qh, *Ql, *Kh, *Kl, *Vh, *Vl;
    cudaGetSymbolAddress((void**)&A3, g_A3);
    cudaGetSymbolAddress((void**)&W3, g_W3);
    cudaGetSymbolAddress((void**)&Qh, g_Qh);
    cudaGetSymbolAddress((void**)&Ql, g_Ql);
    cudaGetSymbolAddress((void**)&Kh, g_Kh);
    cudaGetSymbolAddress((void**)&Kl, g_Kl);
    cudaGetSymbolAddress((void**)&Vh, g_Vh);
    cudaGetSymbolAddress((void**)&Vl, g_Vl);

    cudaFuncSetAttribute(gemm_mma<0>, cudaFuncAttributeMaxDynamicSharedMemorySize, GEMM_SMEM);
    cudaFuncSetAttribute(gemm_mma<1>, cudaFuncAttributeMaxDynamicSharedMemorySize, GEMM_SMEM);
    cudaFuncSetAttribute(attn_mma,    cudaFuncAttributeMaxDynamicSharedMemorySize, ATTN_SMEM);

    const dim3 ggrid(DF / 128, MROWS / 128);           // (8, 32)
    const int convA_blocks = MROWS * DF / (256 * 4);   // 4096
    const int convW_blocks = DF * DF / (256 * 4);      // 1024

    // Q projection -> split bf16 head-major
    conv_split<1><<<convW_blocks, 256>>>(Wq, W3);
    conv_split<0><<<convA_blocks, 256>>>(Q, A3);
    gemm_mma<1><<<ggrid, 256, GEMM_SMEM>>>(A3, W3, bq, nullptr, Qh, Ql);
    // K projection
    conv_split<1><<<convW_blocks, 256>>>(Wk, W3);
    conv_split<0><<<convA_blocks, 256>>>(K, A3);
    gemm_mma<1><<<ggrid, 256, GEMM_SMEM>>>(A3, W3, bk, nullptr, Kh, Kl);
    // V projection
    conv_split<1><<<convW_blocks, 256>>>(Wv, W3);
    conv_split<0><<<convA_blocks, 256>>>(V, A3);
    gemm_mma<1><<<ggrid, 256, GEMM_SMEM>>>(A3, W3, bv, nullptr, Vh, Vl);

    // attention -> writes A3 directly (split [hi|lo|hi])
    attn_mma<<<dim3(SS / 128, NH, BB), 256, ATTN_SMEM>>>(Qh, Ql, Kh, Kl, Vh, Vl, mask, A3);

    // output projection
    conv_split<1><<<convW_blocks, 256>>>(Wo, W3);
    gemm_mma<0><<<ggrid, 256, GEMM_SMEM>>>(A3, W3, bo, out, nullptr, nullptr);
}

// round 8
// speedup vs baseline: 1.2404x; 1.2404x over previous
#include <cuda_runtime.h>
#include <cuda_bf16.h>
#include <cstdint>

#define DF 1024
#define NH 16
#define DH 64
#define BB 2
#define SS 2048
#define MROWS (BB*SS)

#define KW   3072              // split-K width (3 * 1024)
#define KC   64                // bf16 K per SMEM chunk
#define NCHUNK (KW / KC)       // 48
#define NSTAGE 3
#define PITCH  72
#define PITCHB 144
#define OP_BYTES (128 * PITCHB)             // 18432
#define STAGE_BYTES (2 * OP_BYTES)          // 36864
#define GEMM_SMEM (512 + NSTAGE * STAGE_BYTES)  // 111104

// attention smem
#define ATILE   9216                       // one 64x64 bf16 tile, pitch 144
#define ASTRIDE (4 * ATILE + 256)          // Kh,Kl,Vh,Vl = 37120
#define QL_OFF  18432
#define ATTN_SMEM (3 * ASTRIDE)            // 111360

// ---------------------------------------------------------------------------
// Scratch
// ---------------------------------------------------------------------------
__device__ __nv_bfloat16 g_A3v3[3][(size_t)MROWS * KW];  // activations, split [hi|lo|hi]
__device__ __nv_bfloat16 g_W3v4[4][(size_t)DF * KW];     // weights,     split [hi|hi|lo]
__device__ __nv_bfloat16 g_Qh[(size_t)BB * NH * SS * DH];
__device__ __nv_bfloat16 g_Ql[(size_t)BB * NH * SS * DH];
__device__ __nv_bfloat16 g_Kh[(size_t)BB * NH * SS * DH];
__device__ __nv_bfloat16 g_Kl[(size_t)BB * NH * SS * DH];
__device__ __nv_bfloat16 g_Vh[(size_t)BB * NH * SS * DH];
__device__ __nv_bfloat16 g_Vl[(size_t)BB * NH * SS * DH];
__device__ int g_pos[BB * SS];
__device__ int g_cnt[BB];

// ---------------------------------------------------------------------------
// helpers
// ---------------------------------------------------------------------------
__device__ __forceinline__ uint32_t smem_u32(const void* p) {
    uint32_t a;
    asm("{ .reg .u64 t; cvta.to.shared.u64 t, %1; cvt.u32.u64 %0, t; }"
        : "=r"(a) : "l"(p));
    return a;
}

__device__ __forceinline__ void cp_async_16(uint32_t dst, const void* src) {
    asm volatile("cp.async.cg.shared.global [%0], [%1], 16;" :: "r"(dst), "l"(src) : "memory");
}
#define CP_COMMIT() asm volatile("cp.async.commit_group;" ::: "memory")
#define CP_WAIT1()  asm volatile("cp.async.wait_group 1;" ::: "memory")
#define CP_WAIT0()  asm volatile("cp.async.wait_group 0;" ::: "memory")

__device__ __forceinline__ void ldsm_x4(uint32_t& r0, uint32_t& r1, uint32_t& r2,
                                        uint32_t& r3, uint32_t addr) {
    asm volatile("ldmatrix.sync.aligned.m8n8.x4.shared.b16 {%0,%1,%2,%3}, [%4];"
                 : "=r"(r0), "=r"(r1), "=r"(r2), "=r"(r3) : "r"(addr));
}
__device__ __forceinline__ void ldsm_x4_t(uint32_t& r0, uint32_t& r1, uint32_t& r2,
                                          uint32_t& r3, uint32_t addr) {
    asm volatile("ldmatrix.sync.aligned.m8n8.x4.trans.shared.b16 {%0,%1,%2,%3}, [%4];"
                 : "=r"(r0), "=r"(r1), "=r"(r2), "=r"(r3) : "r"(addr));
}

__device__ __forceinline__ void mma16816(float* d, const uint32_t* a, const uint32_t* b) {
    asm volatile(
        "mma.sync.aligned.m16n8k16.row.col.f32.bf16.bf16.f32 "
        "{%0,%1,%2,%3}, {%4,%5,%6,%7}, {%8,%9}, {%0,%1,%2,%3};"
        : "+f"(d[0]), "+f"(d[1]), "+f"(d[2]), "+f"(d[3])
        : "r"(a[0]), "r"(a[1]), "r"(a[2]), "r"(a[3]), "r"(b[0]), "r"(b[1]));
}

__device__ __forceinline__ void split_pack(float x, float y, uint32_t& hp, uint32_t& lp) {
    uint32_t ux = __float_as_uint(x), uy = __float_as_uint(y);
    hp = __byte_perm(ux, uy, 0x7632);
    float lx = x - __uint_as_float(ux & 0xffff0000u);
    float ly = y - __uint_as_float(uy & 0xffff0000u);
    __nv_bfloat162 l2 = __floats2bfloat162_rn(lx, ly);
    lp = *reinterpret_cast<uint32_t*>(&l2);
}

// ---------------------------------------------------------------------------
// mask prefix scan: pos[b][s] = #valid keys before s ; cnt[b] = total valid
// ---------------------------------------------------------------------------
__global__ __launch_bounds__(256) void mask_scan(const int* __restrict__ mask,
                                                 int* __restrict__ pos, int* __restrict__ cnt)
{
    __shared__ int partial[256];
    const int b = blockIdx.x, tid = threadIdx.x;
    const int base = b * SS + tid * 8;
    int v[8], s = 0;
    #pragma unroll
    for (int i = 0; i < 8; i++) { v[i] = (mask[base + i] != 0); s += v[i]; }
    partial[tid] = s;
    __syncthreads();
    for (int off = 1; off < 256; off <<= 1) {
        int t = (tid >= off) ? partial[tid - off] : 0;
        __syncthreads();
        partial[tid] += t;
        __syncthreads();
    }
    int ex = (tid == 0) ? 0 : partial[tid - 1];
    #pragma unroll
    for (int i = 0; i < 8; i++) { pos[base + i] = ex; ex += v[i]; }
    if (tid == 255) cnt[b] = partial[255];
}

// ---------------------------------------------------------------------------
// zero pad rows [cnt, ceil64(cnt)) of compacted K/V (NaN guard for tail tile)
// ---------------------------------------------------------------------------
__global__ void zero_tail(const int* __restrict__ cnt_,
                          __nv_bfloat16* __restrict__ Kh, __nv_bfloat16* __restrict__ Kl,
                          __nv_bfloat16* __restrict__ Vh, __nv_bfloat16* __restrict__ Vl)
{
    const int b = blockIdx.x, h = blockIdx.y;
    const int cnt = cnt_[b];
    const int pad = (cnt + 63) & ~63;
    const int total = (pad - cnt) * DH / 8;      // uint4 units
    const size_t base = ((size_t)(b * NH + h) * SS + cnt) * DH;
    uint4 z = {0, 0, 0, 0};
    for (int i = threadIdx.x; i < total; i += blockDim.x) {
        *reinterpret_cast<uint4*>(Kh + base + (size_t)i * 8) = z;
        *reinterpret_cast<uint4*>(Kl + base + (size_t)i * 8) = z;
        *reinterpret_cast<uint4*>(Vh + base + (size_t)i * 8) = z;
        *reinterpret_cast<uint4*>(Vl + base + (size_t)i * 8) = z;
    }
}

// ---------------------------------------------------------------------------
// Split-bf16 conversions (fused across the 3 inputs / 4 weights)
// ---------------------------------------------------------------------------
__global__ __launch_bounds__(256) void conv_in(const float* __restrict__ Q,
                                               const float* __restrict__ K,
                                               const float* __restrict__ V,
                                               __nv_bfloat16* __restrict__ A3)
{
    const float* X = blockIdx.y == 0 ? Q : (blockIdx.y == 1 ? K : V);
    __nv_bfloat16* Y = A3 + (size_t)blockIdx.y * MROWS * KW;
    int idx = (blockIdx.x * 256 + threadIdx.x) * 4;
    float4 x = *reinterpret_cast<const float4*>(X + idx);
    float v[4] = {x.x, x.y, x.z, x.w};
    __nv_bfloat16 hi[4], lo[4];
    #pragma unroll
    for (int i = 0; i < 4; i++) {
        hi[i] = __float2bfloat16(v[i]);
        lo[i] = __float2bfloat16(v[i] - __bfloat162float(hi[i]));
    }
    uint64_t hip, lop;
    memcpy(&hip, hi, 8);
    memcpy(&lop, lo, 8);
    int r = idx >> 10, k = idx & 1023;
    size_t base = (size_t)r * KW + k;
    *reinterpret_cast<uint64_t*>(Y + base)        = hip;
    *reinterpret_cast<uint64_t*>(Y + base + 1024) = lop;
    *reinterpret_cast<uint64_t*>(Y + base + 2048) = hip;
}

__global__ __launch_bounds__(256) void conv_w(const float* __restrict__ Wq,
                                              const float* __restrict__ Wk,
                                              const float* __restrict__ Wv,
                                              const float* __restrict__ Wo,
                                              __nv_bfloat16* __restrict__ W3)
{
    const float* X = blockIdx.y == 0 ? Wq : (blockIdx.y == 1 ? Wk :
                      (blockIdx.y == 2 ? Wv : Wo));
    __nv_bfloat16* Y = W3 + (size_t)blockIdx.y * DF * KW;
    int idx = (blockIdx.x * 256 + threadIdx.x) * 4;
    float4 x = *reinterpret_cast<const float4*>(X + idx);
    float v[4] = {x.x, x.y, x.z, x.w};
    __nv_bfloat16 hi[4], lo[4];
    #pragma unroll
    for (int i = 0; i < 4; i++) {
        hi[i] = __float2bfloat16(v[i]);
        lo[i] = __float2bfloat16(v[i] - __bfloat162float(hi[i]));
    }
    uint64_t hip, lop;
    memcpy(&hip, hi, 8);
    memcpy(&lop, lo, 8);
    int r = idx >> 10, k = idx & 1023;
    size_t base = (size_t)r * KW + k;
    *reinterpret_cast<uint64_t*>(Y + base)        = hip;
    *reinterpret_cast<uint64_t*>(Y + base + 1024) = hip;
    *reinterpret_cast<uint64_t*>(Y + base + 2048) = lop;
}

// ---------------------------------------------------------------------------
// GEMM mainloop body (shared by both GEMM kernels)
// ---------------------------------------------------------------------------
struct GemmCore {
    float acc[2][8][4];
    int m0w, n0w;

    __device__ __forceinline__ void run(uint32_t sb, int tid, int wid, int lid,
                                        const __nv_bfloat16* Abase,
                                        const __nv_bfloat16* Wbase) {
        m0w = (wid & 3) * 32;
        n0w = (wid >> 2) * 64;
        #pragma unroll
        for (int mi = 0; mi < 2; mi++)
            #pragma unroll
            for (int nj = 0; nj < 8; nj++)
                #pragma unroll
                for (int e = 0; e < 4; e++) acc[mi][nj][e] = 0.f;

        auto load_chunk = [&](int c, int s) {
            const int k0 = c * KC;
            const uint32_t stage = sb + 512 + s * STAGE_BYTES;
            #pragma unroll
            for (int i = 0; i < 8; i++) {
                int seg = i * 256 + tid;
                int op  = seg >> 10;
                int r   = (seg & 1023) >> 3;
                int cs  = seg & 7;
                uint32_t dst = stage + op * OP_BYTES + (uint32_t)(r * PITCHB + cs * 16);
                const __nv_bfloat16* src = (op == 0 ? Abase : Wbase)
                                           + (size_t)r * KW + k0 + cs * 8;
                cp_async_16(dst, src);
            }
        };

        load_chunk(0, 0); CP_COMMIT();
        load_chunk(1, 1); CP_COMMIT();

        for (int c = 0; c < NCHUNK; c++) {
            const int s = c % NSTAGE;
            CP_WAIT1();
            __syncthreads();
            int cn = c + 2;
            if (cn < NCHUNK) load_chunk(cn, cn % NSTAGE);
            CP_COMMIT();

            const uint32_t sA = sb + 512 + s * STAGE_BYTES;
            const uint32_t sW = sA + OP_BYTES;
            #pragma unroll
            for (int kk = 0; kk < 4; kk++) {
                uint32_t a[2][4];
                #pragma unroll
                for (int mi = 0; mi < 2; mi++) {
                    uint32_t addr = sA + (uint32_t)((m0w + mi * 16 + (lid & 15)) * PITCHB
                                     + kk * 32 + ((lid >> 4) << 4));
                    ldsm_x4(a[mi][0], a[mi][1], a[mi][2], a[mi][3], addr);
                }
                uint32_t b[8][2];
                #pragma unroll
                for (int ni = 0; ni < 4; ni++) {
                    uint32_t addr = sW + (uint32_t)((n0w + ni * 16 + (lid & 7)
                                     + ((lid >> 4) & 1) * 8) * PITCHB
                                     + kk * 32 + (((lid >> 3) & 1) << 4));
                    uint32_t r0, r1, r2, r3;
                    ldsm_x4(r0, r1, r2, r3, addr);
                    b[2 * ni][0] = r0; b[2 * ni][1] = r1;
                    b[2 * ni + 1][0] = r2; b[2 * ni + 1][1] = r3;
                }
                #pragma unroll
                for (int mi = 0; mi < 2; mi++)
                    #pragma unroll
                    for (int nj = 0; nj < 8; nj++)
                        mma16816(acc[mi][nj], a[mi], b[nj]);
            }
            __syncthreads();
        }
        CP_WAIT0();
    }
};

// ---------------------------------------------------------------------------
// Fused QKV projection GEMM. z=0: Q (dense head-major). z=1: K, z=2: V
// (compacted head-major via pos[] / mask).
// ---------------------------------------------------------------------------
__global__ void __launch_bounds__(256, 1)
gemm_qkv(const __nv_bfloat16* __restrict__ A3, const __nv_bfloat16* __restrict__ W3,
         const float* __restrict__ bq, const float* __restrict__ bk,
         const float* __restrict__ bv,
         const int* __restrict__ mask, const int* __restrict__ pos,
         __nv_bfloat16* __restrict__ Qh, __nv_bfloat16* __restrict__ Ql,
         __nv_bfloat16* __restrict__ Kh, __nv_bfloat16* __restrict__ Kl,
         __nv_bfloat16* __restrict__ Vh, __nv_bfloat16* __restrict__ Vl)
{
    extern __shared__ char smem[];
    const uint32_t sb = smem_u32(smem);
    const int tid = threadIdx.x, wid = tid >> 5, lid = tid & 31;
    const int z = blockIdx.z;
    const int m0 = blockIdx.y * 128, n0 = blockIdx.x * 128;

    const float* bias = (z == 0) ? bq : (z == 1) ? bk : bv;
    float* bias_s = (float*)smem;
    if (tid < 128) bias_s[tid] = bias[n0 + tid];

    __nv_bfloat16* H = (z == 0) ? Qh : (z == 1) ? Kh : Vh;
    __nv_bfloat16* L = (z == 0) ? Ql : (z == 1) ? Kl : Vl;
    const bool compact = (z > 0);

    GemmCore core;
    core.run(sb, tid, wid, lid,
             A3 + (size_t)z * MROWS * KW + (size_t)m0 * KW,
             W3 + (size_t)z * DF * KW + (size_t)n0 * KW);

    const int g = lid >> 2, t = lid & 3;
    #pragma unroll
    for (int mi = 0; mi < 2; mi++) {
        #pragma unroll
        for (int nj = 0; nj < 8; nj++) {
            int colrel = core.n0w + nj * 8 + 2 * t;
            int col = n0 + colrel;
            int hh = col >> 6, dh = col & 63;
            float c0 = core.acc[mi][nj][0] + bias_s[colrel];
            float c1 = core.acc[mi][nj][1] + bias_s[colrel + 1];
            float c2 = core.acc[mi][nj][2] + bias_s[colrel];
            float c3 = core.acc[mi][nj][3] + bias_s[colrel + 1];
            #pragma unroll
            for (int rr = 0; rr < 2; rr++) {
                int row = m0 + core.m0w + mi * 16 + g + rr * 8;
                int bb_ = row >> 11, sidx = row & 2047;
                int drow = sidx;
                bool store = true;
                if (compact) {
                    store = (mask[bb_ * SS + sidx] != 0);
                    drow  = pos[bb_ * SS + sidx];
                }
                if (store) {
                    size_t dst = ((size_t)(bb_ * NH + hh) * SS + drow) * DH + dh;
                    uint32_t hp, lp;
                    if (rr == 0) split_pack(c0, c1, hp, lp);
                    else         split_pack(c2, c3, hp, lp);
                    *reinterpret_cast<uint32_t*>(H + dst) = hp;
                    *reinterpret_cast<uint32_t*>(L + dst) = lp;
                }
            }
        }
    }
}

// ---------------------------------------------------------------------------
// Output projection GEMM: fp32 out
// ---------------------------------------------------------------------------
__global__ void __launch_bounds__(256, 1)
gemm_out(const __nv_bfloat16* __restrict__ A3, const __nv_bfloat16* __restrict__ W3,
         const float* __restrict__ bias, float* __restrict__ C)
{
    extern __shared__ char smem[];
    const uint32_t sb = smem_u32(smem);
    const int tid = threadIdx.x, wid = tid >> 5, lid = tid & 31;
    const int m0 = blockIdx.y * 128, n0 = blockIdx.x * 128;

    float* bias_s = (float*)smem;
    if (tid < 128) bias_s[tid] = bias[n0 + tid];

    GemmCore core;
    core.run(sb, tid, wid, lid, A3 + (size_t)m0 * KW, W3 + (size_t)n0 * KW);

    const int g = lid >> 2, t = lid & 3;
    #pragma unroll
    for (int mi = 0; mi < 2; mi++) {
        #pragma unroll
        for (int nj = 0; nj < 8; nj++) {
            int colrel = core.n0w + nj * 8 + 2 * t;
            int col = n0 + colrel;
            int row0 = m0 + core.m0w + mi * 16 + g;
            float2 v0 = {core.acc[mi][nj][0] + bias_s[colrel],
                         core.acc[mi][nj][1] + bias_s[colrel + 1]};
            float2 v1 = {core.acc[mi][nj][2] + bias_s[colrel],
                         core.acc[mi][nj][3] + bias_s[colrel + 1]};
            *reinterpret_cast<float2*>(C + (size_t)row0 * DF + col) = v0;
            *reinterpret_cast<float2*>(C + (size_t)(row0 + 8) * DF + col) = v1;
        }
    }
}

// ---------------------------------------------------------------------------
// FlashAttention-2 on mma.sync over COMPACTED keys (exact: masked keys
// contribute exactly 0). Tail tile masked by index >= cnt.
// ---------------------------------------------------------------------------
__global__ void __launch_bounds__(256, 1)
attn_mma(const __nv_bfloat16* __restrict__ Qh_, const __nv_bfloat16* __restrict__ Ql_,
         const __nv_bfloat16* __restrict__ Kh_, const __nv_bfloat16* __restrict__ Kl_,
         const __nv_bfloat16* __restrict__ Vh_, const __nv_bfloat16* __restrict__ Vl_,
         const int* __restrict__ cnt_, __nv_bfloat16* __restrict__ A3out)
{
    extern __shared__ char smem[];
    const uint32_t sb = smem_u32(smem);
    const int tid = threadIdx.x, wid = tid >> 5, lid = tid & 31;
    const int g = lid >> 2, t4 = lid & 3;
    const int b = blockIdx.z, h = blockIdx.y;
    const int bh = b * NH + h;
    const int q0 = blockIdx.x * 128;
    const int m0w = wid * 16;
    const float SC = 0.03125f;

    const int cnt = cnt_[b];
    const int nt = (cnt + 63) >> 6;

    // ---- stage Q (hi,lo) through smem into register a-frags ----
    {
        const size_t qbase = ((size_t)bh * SS + q0);
        #pragma unroll
        for (int i = 0; i < 4; i++) {
            int seg = i * 256 + tid;
            int row = seg >> 3, cs = seg & 7;
            const size_t src = (qbase + row) * DH + cs * 8;
            uint32_t d = sb + (uint32_t)(row * PITCHB + cs * 16);
            cp_async_16(d,          Qh_ + src);
            cp_async_16(d + QL_OFF, Ql_ + src);
        }
    }
    CP_COMMIT(); CP_WAIT0(); __syncthreads();

    uint32_t qh[4][4], ql[4][4];
    #pragma unroll
    for (int kk = 0; kk < 4; kk++) {
        uint32_t a = sb + (uint32_t)((m0w + (lid & 15)) * PITCHB + kk * 32 + ((lid >> 4) << 4));
        ldsm_x4(qh[kk][0], qh[kk][1], qh[kk][2], qh[kk][3], a);
        ldsm_x4(ql[kk][0], ql[kk][1], ql[kk][2], ql[kk][3], a + QL_OFF);
    }
    __syncthreads();

    auto load_tile = [&](int ti, int st) {
        const uint32_t stage = sb + st * ASTRIDE;
        const size_t kbase = ((size_t)bh * SS + ti * 64);
        #pragma unroll
        for (int i = 0; i < 2; i++) {
            int seg = i * 256 + tid;
            int row = seg >> 3, cs = seg & 7;
            size_t src = (kbase + row) * DH + cs * 8;
            uint32_t d = stage + (uint32_t)(row * PITCHB + cs * 16);
            cp_async_16(d,             Kh_ + src);
            cp_async_16(d + ATILE,     Kl_ + src);
            cp_async_16(d + 2 * ATILE, Vh_ + src);
            cp_async_16(d + 3 * ATILE, Vl_ + src);
        }
    };

    float m0 = -1e30f, m1 = -1e30f, l0 = 0.f, l1 = 0.f;
    float o[8][4];
    #pragma unroll
    for (int nj = 0; nj < 8; nj++)
        #pragma unroll
        for (int e = 0; e < 4; e++) o[nj][e] = 0.f;

    if (0 < nt) load_tile(0, 0);
    CP_COMMIT();
    if (1 < nt) load_tile(1, 1);
    CP_COMMIT();

    for (int ti = 0; ti < nt; ti++) {
        const int st = ti % 3;
        CP_WAIT1();
        __syncthreads();
        if (ti + 2 < nt) load_tile(ti + 2, (ti + 2) % 3);
        CP_COMMIT();

        const uint32_t sK  = sb + st * ASTRIDE;
        const uint32_t sKl = sK + ATILE, sV = sK + 2 * ATILE, sVl = sK + 3 * ATILE;

        // ---- S = Qh Kh^T + Ql Kh^T + Qh Kl^T ----
        float s[8][4];
        #pragma unroll
        for (int nj = 0; nj < 8; nj++)
            #pragma unroll
            for (int e = 0; e < 4; e++) s[nj][e] = 0.f;

        #pragma unroll
        for (int kk = 0; kk < 4; kk++) {
            uint32_t kb[4][4];
            #pragma unroll
            for (int ni = 0; ni < 4; ni++) {
                uint32_t a = sK + (uint32_t)((ni * 16 + (lid & 7) + ((lid >> 4) & 1) * 8) * PITCHB
                             + kk * 32 + (((lid >> 3) & 1) << 4));
                ldsm_x4(kb[ni][0], kb[ni][1], kb[ni][2], kb[ni][3], a);
            }
            #pragma unroll
            for (int nj = 0; nj < 8; nj++) mma16816(s[nj], qh[kk], &kb[nj >> 1][(nj & 1) * 2]);
            #pragma unroll
            for (int nj = 0; nj < 8; nj++) mma16816(s[nj], ql[kk], &kb[nj >> 1][(nj & 1) * 2]);
            #pragma unroll
            for (int ni = 0; ni < 4; ni++) {
                uint32_t a = sKl + (uint32_t)((ni * 16 + (lid & 7) + ((lid >> 4) & 1) * 8) * PITCHB
                             + kk * 32 + (((lid >> 3) & 1) << 4));
                ldsm_x4(kb[ni][0], kb[ni][1], kb[ni][2], kb[ni][3], a);
            }
            #pragma unroll
            for (int nj = 0; nj < 8; nj++) mma16816(s[nj], qh[kk], &kb[nj >> 1][(nj & 1) * 2]);
        }

        // ---- scale + tail mask + online softmax ----
        const int kbase_idx = ti * 64;
        float tmax0 = -1e30f, tmax1 = -1e30f;
        #pragma unroll
        for (int nj = 0; nj < 8; nj++) {
            int k0i = kbase_idx + nj * 8 + 2 * t4;
            bool v0 = k0i < cnt, v1 = (k0i + 1) < cnt;
            float s0 = v0 ? s[nj][0] * SC : -1e9f;
            float s1 = v1 ? s[nj][1] * SC : -1e9f;
            float s2 = v0 ? s[nj][2] * SC : -1e9f;
            float s3 = v1 ? s[nj][3] * SC : -1e9f;
            s[nj][0] = s0; s[nj][1] = s1; s[nj][2] = s2; s[nj][3] = s3;
            tmax0 = fmaxf(tmax0, fmaxf(s0, s1));
            tmax1 = fmaxf(tmax1, fmaxf(s2, s3));
        }
        tmax0 = fmaxf(tmax0, __shfl_xor_sync(0xffffffffu, tmax0, 1));
        tmax0 = fmaxf(tmax0, __shfl_xor_sync(0xffffffffu, tmax0, 2));
        tmax1 = fmaxf(tmax1, __shfl_xor_sync(0xffffffffu, tmax1, 1));
        tmax1 = fmaxf(tmax1, __shfl_xor_sync(0xffffffffu, tmax1, 2));

        float mn0 = fmaxf(m0, tmax0), mn1 = fmaxf(m1, tmax1);
        float sc0 = __expf(m0 - mn0), sc1 = __expf(m1 - mn1);
        m0 = mn0; m1 = mn1;
        l0 *= sc0; l1 *= sc1;
        #pragma unroll
        for (int nj = 0; nj < 8; nj++) {
            o[nj][0] *= sc0; o[nj][1] *= sc0;
            o[nj][2] *= sc1; o[nj][3] *= sc1;
        }
        #pragma unroll
        for (int nj = 0; nj < 8; nj++) {
            float p0 = __expf(s[nj][0] - m0);
            float p1 = __expf(s[nj][1] - m0);
            float p2 = __expf(s[nj][2] - m1);
            float p3 = __expf(s[nj][3] - m1);
            s[nj][0] = p0; s[nj][1] = p1; s[nj][2] = p2; s[nj][3] = p3;
            l0 += p0 + p1; l1 += p2 + p3;
        }

        // ---- O += Ph Vh + Pl Vh + Ph Vl ----
        #pragma unroll
        for (int kk = 0; kk < 4; kk++) {
            uint32_t ah[4], al[4];
            split_pack(s[2 * kk][0],     s[2 * kk][1],     ah[0], al[0]);
            split_pack(s[2 * kk][2],     s[2 * kk][3],     ah[1], al[1]);
            split_pack(s[2 * kk + 1][0], s[2 * kk + 1][1], ah[2], al[2]);
            split_pack(s[2 * kk + 1][2], s[2 * kk + 1][3], ah[3], al[3]);

            uint32_t vb[4][4];
            #pragma unroll
            for (int njp = 0; njp < 4; njp++) {
                uint32_t a = sV + (uint32_t)((16 * kk + (lid & 7) + ((lid >> 3) & 1) * 8) * PITCHB
                             + (16 * njp + ((lid >> 4) & 1) * 8) * 2);
                ldsm_x4_t(vb[njp][0], vb[njp][1], vb[njp][2], vb[njp][3], a);
            }
            #pragma unroll
            for (int nj = 0; nj < 8; nj++) mma16816(o[nj], ah, &vb[nj >> 1][(nj & 1) * 2]);
            #pragma unroll
            for (int nj = 0; nj < 8; nj++) mma16816(o[nj], al, &vb[nj >> 1][(nj & 1) * 2]);
            #pragma unroll
            for (int njp = 0; njp < 4; njp++) {
                uint32_t a = sVl + (uint32_t)((16 * kk + (lid & 7) + ((lid >> 3) & 1) * 8) * PITCHB
                             + (16 * njp + ((lid >> 4) & 1) * 8) * 2);
                ldsm_x4_t(vb[njp][0], vb[njp][1], vb[njp][2], vb[njp][3], a);
            }
            #pragma unroll
            for (int nj = 0; nj < 8; nj++) mma16816(o[nj], ah, &vb[nj >> 1][(nj & 1) * 2]);
        }
        __syncthreads();
    }
    CP_WAIT0();

    // ---- finalize + write split bf16 straight into A3 [hi|lo|hi] ----
    l0 += __shfl_xor_sync(0xffffffffu, l0, 1);
    l0 += __shfl_xor_sync(0xffffffffu, l0, 2);
    l1 += __shfl_xor_sync(0xffffffffu, l1, 1);
    l1 += __shfl_xor_sync(0xffffffffu, l1, 2);
    float inv0 = 1.f / l0, inv1 = 1.f / l1;

    const int srow = q0 + m0w + g;
    size_t r0 = (size_t)(b * SS + srow) * KW;
    size_t r1 = r0 + (size_t)8 * KW;
    const int colbase = h * DH;

    #pragma unroll
    for (int nj = 0; nj < 8; nj++) {
        int c = colbase + nj * 8 + 2 * t4;
        uint32_t hp, lp;
        split_pack(o[nj][0] * inv0, o[nj][1] * inv0, hp, lp);
        *reinterpret_cast<uint32_t*>(A3out + r0 + c)        = hp;
        *reinterpret_cast<uint32_t*>(A3out + r0 + 1024 + c) = lp;
        *reinterpret_cast<uint32_t*>(A3out + r0 + 2048 + c) = hp;
        split_pack(o[nj][2] * inv1, o[nj][3] * inv1, hp, lp);
        *reinterpret_cast<uint32_t*>(A3out + r1 + c)        = hp;
        *reinterpret_cast<uint32_t*>(A3out + r1 + 1024 + c) = lp;
        *reinterpret_cast<uint32_t*>(A3out + r1 + 2048 + c) = hp;
    }
}

// ---------------------------------------------------------------------------
// launch
// ---------------------------------------------------------------------------
extern "C" void kernel_launch(void* const* d_in, const int* in_sizes, int n_in,
                              void* d_out, int out_size)
{
    const float* Q    = (const float*)d_in[0];
    const float* K    = (const float*)d_in[1];
    const float* V    = (const float*)d_in[2];
    const int*   mask = (const int*)  d_in[3];
    const float* Wq   = (const float*)d_in[4];
    const float* bq   = (const float*)d_in[5];
    const float* Wk   = (const float*)d_in[6];
    const float* bk   = (const float*)d_in[7];
    const float* Wv   = (const float*)d_in[8];
    const float* bv   = (const float*)d_in[9];
    const float* Wo   = (const float*)d_in[10];
    const float* bo   = (const float*)d_in[11];
    float* out = (float*)d_out;

    __nv_bfloat16 *A3, *W3, *Qh, *Ql, *Kh, *Kl, *Vh, *Vl;
    int *pos, *cnt;
    cudaGetSymbolAddress((void**)&A3, g_A3v3);
    cudaGetSymbolAddress((void**)&W3, g_W3v4);
    cudaGetSymbolAddress((void**)&Qh, g_Qh);
    cudaGetSymbolAddress((void**)&Ql, g_Ql);
    cudaGetSymbolAddress((void**)&Kh, g_Kh);
    cudaGetSymbolAddress((void**)&Kl, g_Kl);
    cudaGetSymbolAddress((void**)&Vh, g_Vh);
    cudaGetSymbolAddress((void**)&Vl, g_Vl);
    cudaGetSymbolAddress((void**)&pos, g_pos);
    cudaGetSymbolAddress((void**)&cnt, g_cnt);

    cudaFuncSetAttribute(gemm_qkv, cudaFuncAttributeMaxDynamicSharedMemorySize, GEMM_SMEM);
    cudaFuncSetAttribute(gemm_out, cudaFuncAttributeMaxDynamicSharedMemorySize, GEMM_SMEM);
    cudaFuncSetAttribute(attn_mma, cudaFuncAttributeMaxDynamicSharedMemorySize, ATTN_SMEM);

    mask_scan<<<BB, 256>>>(mask, pos, cnt);
    conv_w<<<dim3(DF * DF / 1024, 4), 256>>>(Wq, Wk, Wv, Wo, W3);
    conv_in<<<dim3(MROWS * DF / 1024, 3), 256>>>(Q, K, V, A3);

    gemm_qkv<<<dim3(DF / 128, MROWS / 128, 3), 256, GEMM_SMEM>>>(
        A3, W3, bq, bk, bv, mask, pos, Qh, Ql, Kh, Kl, Vh, Vl);

    zero_tail<<<dim3(BB, NH), 256>>>(cnt, Kh, Kl, Vh, Vl);

    attn_mma<<<dim3(SS / 128, NH, BB), 256, ATTN_SMEM>>>(Qh, Ql, Kh, Kl, Vh, Vl, cnt, A3);

    gemm_out<<<dim3(DF / 128, MROWS / 128), 256, GEMM_SMEM>>>(
        A3, W3 + (size_t)3 * DF * KW, bo, out);
}

// round 9
// speedup vs baseline: 1.4499x; 1.1689x over previous
#include <cuda_runtime.h>
#include <cuda_bf16.h>
#include <cstdint>

#define DF 1024
#define NH 16
#define DH 64
#define BB 2
#define SS 2048
#define MROWS (BB*SS)

#define KW   3072              // split-K width (3 * 1024)
#define KC   64                // bf16 K per SMEM chunk
#define NCHUNK (KW / KC)       // 48
#define NSTAGE 3
#define PITCH  72
#define PITCHB 144
#define OP_BYTES (128 * PITCHB)             // 18432
#define STAGE_BYTES (2 * OP_BYTES)          // 36864
#define GEMM_SMEM (512 + NSTAGE * STAGE_BYTES)  // 111104

// attention smem
#define ATILE   9216                       // one 64x64 bf16 tile, pitch 144
#define ASTRIDE (4 * ATILE + 256)          // Kh,Kl,Vh,Vl = 37120
#define QL_OFF  18432
#define ATTN_SMEM (3 * ASTRIDE)            // 111360

// ---------------------------------------------------------------------------
// Scratch
// ---------------------------------------------------------------------------
__device__ __nv_bfloat16 g_A3v3[3][(size_t)MROWS * KW];  // activations, split [hi|lo|hi]
__device__ __nv_bfloat16 g_W3v4[4][(size_t)DF * KW];     // weights,     split [hi|hi|lo]
__device__ __nv_bfloat16 g_Qh[(size_t)BB * NH * SS * DH];
__device__ __nv_bfloat16 g_Ql[(size_t)BB * NH * SS * DH];
__device__ __nv_bfloat16 g_Kh[(size_t)BB * NH * SS * DH];
__device__ __nv_bfloat16 g_Kl[(size_t)BB * NH * SS * DH];
__device__ __nv_bfloat16 g_Vh[(size_t)BB * NH * SS * DH];
__device__ __nv_bfloat16 g_Vl[(size_t)BB * NH * SS * DH];
__device__ int g_pos[BB * SS];
__device__ int g_cnt[BB];

// ---------------------------------------------------------------------------
// helpers
// ---------------------------------------------------------------------------
__device__ __forceinline__ uint32_t smem_u32(const void* p) {
    uint32_t a;
    asm("{ .reg .u64 t; cvta.to.shared.u64 t, %1; cvt.u32.u64 %0, t; }"
        : "=r"(a) : "l"(p));
    return a;
}

__device__ __forceinline__ void cp_async_16(uint32_t dst, const void* src) {
    asm volatile("cp.async.cg.shared.global [%0], [%1], 16;" :: "r"(dst), "l"(src) : "memory");
}
#define CP_COMMIT() asm volatile("cp.async.commit_group;" ::: "memory")
#define CP_WAIT1()  asm volatile("cp.async.wait_group 1;" ::: "memory")
#define CP_WAIT0()  asm volatile("cp.async.wait_group 0;" ::: "memory")

__device__ __forceinline__ void ldsm_x4(uint32_t& r0, uint32_t& r1, uint32_t& r2,
                                        uint32_t& r3, uint32_t addr) {
    asm volatile("ldmatrix.sync.aligned.m8n8.x4.shared.b16 {%0,%1,%2,%3}, [%4];"
                 : "=r"(r0), "=r"(r1), "=r"(r2), "=r"(r3) : "r"(addr));
}
__device__ __forceinline__ void ldsm_x4_t(uint32_t& r0, uint32_t& r1, uint32_t& r2,
                                          uint32_t& r3, uint32_t addr) {
    asm volatile("ldmatrix.sync.aligned.m8n8.x4.trans.shared.b16 {%0,%1,%2,%3}, [%4];"
                 : "=r"(r0), "=r"(r1), "=r"(r2), "=r"(r3) : "r"(addr));
}

__device__ __forceinline__ void mma16816(float* d, const uint32_t* a, const uint32_t* b) {
    asm volatile(
        "mma.sync.aligned.m16n8k16.row.col.f32.bf16.bf16.f32 "
        "{%0,%1,%2,%3}, {%4,%5,%6,%7}, {%8,%9}, {%0,%1,%2,%3};"
        : "+f"(d[0]), "+f"(d[1]), "+f"(d[2]), "+f"(d[3])
        : "r"(a[0]), "r"(a[1]), "r"(a[2]), "r"(a[3]), "r"(b[0]), "r"(b[1]));
}

__device__ __forceinline__ void split_pack(float x, float y, uint32_t& hp, uint32_t& lp) {
    uint32_t ux = __float_as_uint(x), uy = __float_as_uint(y);
    hp = __byte_perm(ux, uy, 0x7632);
    float lx = x - __uint_as_float(ux & 0xffff0000u);
    float ly = y - __uint_as_float(uy & 0xffff0000u);
    __nv_bfloat162 l2 = __floats2bfloat162_rn(lx, ly);
    lp = *reinterpret_cast<uint32_t*>(&l2);
}

// ---------------------------------------------------------------------------
// mask prefix scan: pos[b][s] = #valid keys before s ; cnt[b] = total valid
// ---------------------------------------------------------------------------
__global__ __launch_bounds__(256) void mask_scan(const int* __restrict__ mask,
                                                 int* __restrict__ pos, int* __restrict__ cnt)
{
    __shared__ int partial[256];
    const int b = blockIdx.x, tid = threadIdx.x;
    const int base = b * SS + tid * 8;
    int v[8], s = 0;
    #pragma unroll
    for (int i = 0; i < 8; i++) { v[i] = (mask[base + i] != 0); s += v[i]; }
    partial[tid] = s;
    __syncthreads();
    for (int off = 1; off < 256; off <<= 1) {
        int t = (tid >= off) ? partial[tid - off] : 0;
        __syncthreads();
        partial[tid] += t;
        __syncthreads();
    }
    int ex = (tid == 0) ? 0 : partial[tid - 1];
    #pragma unroll
    for (int i = 0; i < 8; i++) { pos[base + i] = ex; ex += v[i]; }
    if (tid == 255) cnt[b] = partial[255];
}

// ---------------------------------------------------------------------------
// zero pad rows [cnt, ceil64(cnt)) of compacted K/V (NaN guard for tail tile)
// ---------------------------------------------------------------------------
__global__ void zero_tail(const int* __restrict__ cnt_,
                          __nv_bfloat16* __restrict__ Kh, __nv_bfloat16* __restrict__ Kl,
                          __nv_bfloat16* __restrict__ Vh, __nv_bfloat16* __restrict__ Vl)
{
    const int b = blockIdx.x, h = blockIdx.y;
    const int cnt = cnt_[b];
    const int pad = (cnt + 63) & ~63;
    const int total = (pad - cnt) * DH / 8;      // uint4 units
    const size_t base = ((size_t)(b * NH + h) * SS + cnt) * DH;
    uint4 z = {0, 0, 0, 0};
    for (int i = threadIdx.x; i < total; i += blockDim.x) {
        *reinterpret_cast<uint4*>(Kh + base + (size_t)i * 8) = z;
        *reinterpret_cast<uint4*>(Kl + base + (size_t)i * 8) = z;
        *reinterpret_cast<uint4*>(Vh + base + (size_t)i * 8) = z;
        *reinterpret_cast<uint4*>(Vl + base + (size_t)i * 8) = z;
    }
}

// ---------------------------------------------------------------------------
// Split-bf16 conversions (fused across the 3 inputs / 4 weights)
// ---------------------------------------------------------------------------
__global__ __launch_bounds__(256) void conv_in(const float* __restrict__ Q,
                                               const float* __restrict__ K,
                                               const float* __restrict__ V,
                                               __nv_bfloat16* __restrict__ A3)
{
    const float* X = blockIdx.y == 0 ? Q : (blockIdx.y == 1 ? K : V);
    __nv_bfloat16* Y = A3 + (size_t)blockIdx.y * MROWS * KW;
    int idx = (blockIdx.x * 256 + threadIdx.x) * 4;
    float4 x = *reinterpret_cast<const float4*>(X + idx);
    float v[4] = {x.x, x.y, x.z, x.w};
    __nv_bfloat16 hi[4], lo[4];
    #pragma unroll
    for (int i = 0; i < 4; i++) {
        hi[i] = __float2bfloat16(v[i]);
        lo[i] = __float2bfloat16(v[i] - __bfloat162float(hi[i]));
    }
    uint64_t hip, lop;
    memcpy(&hip, hi, 8);
    memcpy(&lop, lo, 8);
    int r = idx >> 10, k = idx & 1023;
    size_t base = (size_t)r * KW + k;
    *reinterpret_cast<uint64_t*>(Y + base)        = hip;
    *reinterpret_cast<uint64_t*>(Y + base + 1024) = lop;
    *reinterpret_cast<uint64_t*>(Y + base + 2048) = hip;
}

__global__ __launch_bounds__(256) void conv_w(const float* __restrict__ Wq,
                                              const float* __restrict__ Wk,
                                              const float* __restrict__ Wv,
                                              const float* __restrict__ Wo,
                                              __nv_bfloat16* __restrict__ W3)
{
    const float* X = blockIdx.y == 0 ? Wq : (blockIdx.y == 1 ? Wk :
                      (blockIdx.y == 2 ? Wv : Wo));
    __nv_bfloat16* Y = W3 + (size_t)blockIdx.y * DF * KW;
    int idx = (blockIdx.x * 256 + threadIdx.x) * 4;
    float4 x = *reinterpret_cast<const float4*>(X + idx);
    float v[4] = {x.x, x.y, x.z, x.w};
    __nv_bfloat16 hi[4], lo[4];
    #pragma unroll
    for (int i = 0; i < 4; i++) {
        hi[i] = __float2bfloat16(v[i]);
        lo[i] = __float2bfloat16(v[i] - __bfloat162float(hi[i]));
    }
    uint64_t hip, lop;
    memcpy(&hip, hi, 8);
    memcpy(&lop, lo, 8);
    int r = idx >> 10, k = idx & 1023;
    size_t base = (size_t)r * KW + k;
    *reinterpret_cast<uint64_t*>(Y + base)        = hip;
    *reinterpret_cast<uint64_t*>(Y + base + 1024) = hip;
    *reinterpret_cast<uint64_t*>(Y + base + 2048) = lop;
}

// ---------------------------------------------------------------------------
// GEMM mainloop body: 128 threads / 4 warps (2M x 2N), warp tile 64x64
// (mi=4, nj=8). Halved smem read traffic per MAC vs 32x64 warp tiles,
// and small enough (regs+smem) for 2 CTAs/SM.
// ---------------------------------------------------------------------------
struct GemmCore {
    float acc[4][8][4];
    int m0w, n0w;

    __device__ __forceinline__ void run(uint32_t sb, int tid, int wid, int lid,
                                        const __nv_bfloat16* Abase,
                                        const __nv_bfloat16* Wbase) {
        m0w = (wid & 1) * 64;
        n0w = (wid >> 1) * 64;
        #pragma unroll
        for (int mi = 0; mi < 4; mi++)
            #pragma unroll
            for (int nj = 0; nj < 8; nj++)
                #pragma unroll
                for (int e = 0; e < 4; e++) acc[mi][nj][e] = 0.f;

        auto load_chunk = [&](int c, int s) {
            const int k0 = c * KC;
            const uint32_t stage = sb + 512 + s * STAGE_BYTES;
            #pragma unroll
            for (int i = 0; i < 16; i++) {
                int seg = i * 128 + tid;
                int op  = seg >> 10;
                int r   = (seg & 1023) >> 3;
                int cs  = seg & 7;
                uint32_t dst = stage + op * OP_BYTES + (uint32_t)(r * PITCHB + cs * 16);
                const __nv_bfloat16* src = (op == 0 ? Abase : Wbase)
                                           + (size_t)r * KW + k0 + cs * 8;
                cp_async_16(dst, src);
            }
        };

        load_chunk(0, 0); CP_COMMIT();
        load_chunk(1, 1); CP_COMMIT();

        for (int c = 0; c < NCHUNK; c++) {
            const int s = c % NSTAGE;
            CP_WAIT1();
            __syncthreads();
            int cn = c + 2;
            if (cn < NCHUNK) load_chunk(cn, cn % NSTAGE);
            CP_COMMIT();

            const uint32_t sA = sb + 512 + s * STAGE_BYTES;
            const uint32_t sW = sA + OP_BYTES;
            #pragma unroll
            for (int kk = 0; kk < 4; kk++) {
                uint32_t a[4][4];
                #pragma unroll
                for (int mi = 0; mi < 4; mi++) {
                    uint32_t addr = sA + (uint32_t)((m0w + mi * 16 + (lid & 15)) * PITCHB
                                     + kk * 32 + ((lid >> 4) << 4));
                    ldsm_x4(a[mi][0], a[mi][1], a[mi][2], a[mi][3], addr);
                }
                uint32_t b[8][2];
                #pragma unroll
                for (int ni = 0; ni < 4; ni++) {
                    uint32_t addr = sW + (uint32_t)((n0w + ni * 16 + (lid & 7)
                                     + ((lid >> 4) & 1) * 8) * PITCHB
                                     + kk * 32 + (((lid >> 3) & 1) << 4));
                    uint32_t r0, r1, r2, r3;
                    ldsm_x4(r0, r1, r2, r3, addr);
                    b[2 * ni][0] = r0; b[2 * ni][1] = r1;
                    b[2 * ni + 1][0] = r2; b[2 * ni + 1][1] = r3;
                }
                #pragma unroll
                for (int mi = 0; mi < 4; mi++)
                    #pragma unroll
                    for (int nj = 0; nj < 8; nj++)
                        mma16816(acc[mi][nj], a[mi], b[nj]);
            }
            __syncthreads();
        }
        CP_WAIT0();
    }
};

// ---------------------------------------------------------------------------
// Fused QKV projection GEMM. z=0: Q (dense head-major). z=1: K, z=2: V
// (compacted head-major via pos[] / mask).
// ---------------------------------------------------------------------------
__global__ void __launch_bounds__(128, 2)
gemm_qkv(const __nv_bfloat16* __restrict__ A3, const __nv_bfloat16* __restrict__ W3,
         const float* __restrict__ bq, const float* __restrict__ bk,
         const float* __restrict__ bv,
         const int* __restrict__ mask, const int* __restrict__ pos,
         __nv_bfloat16* __restrict__ Qh, __nv_bfloat16* __restrict__ Ql,
         __nv_bfloat16* __restrict__ Kh, __nv_bfloat16* __restrict__ Kl,
         __nv_bfloat16* __restrict__ Vh, __nv_bfloat16* __restrict__ Vl)
{
    extern __shared__ char smem[];
    const uint32_t sb = smem_u32(smem);
    const int tid = threadIdx.x, wid = tid >> 5, lid = tid & 31;
    const int z = blockIdx.z;
    const int m0 = blockIdx.y * 128, n0 = blockIdx.x * 128;

    const float* bias = (z == 0) ? bq : (z == 1) ? bk : bv;
    float* bias_s = (float*)smem;
    if (tid < 128) bias_s[tid] = bias[n0 + tid];

    __nv_bfloat16* H = (z == 0) ? Qh : (z == 1) ? Kh : Vh;
    __nv_bfloat16* L = (z == 0) ? Ql : (z == 1) ? Kl : Vl;
    const bool compact = (z > 0);

    GemmCore core;
    core.run(sb, tid, wid, lid,
             A3 + (size_t)z * MROWS * KW + (size_t)m0 * KW,
             W3 + (size_t)z * DF * KW + (size_t)n0 * KW);

    const int g = lid >> 2, t = lid & 3;
    #pragma unroll
    for (int mi = 0; mi < 4; mi++) {
        #pragma unroll
        for (int nj = 0; nj < 8; nj++) {
            int colrel = core.n0w + nj * 8 + 2 * t;
            int col = n0 + colrel;
            int hh = col >> 6, dh = col & 63;
            float c0 = core.acc[mi][nj][0] + bias_s[colrel];
            float c1 = core.acc[mi][nj][1] + bias_s[colrel + 1];
            float c2 = core.acc[mi][nj][2] + bias_s[colrel];
            float c3 = core.acc[mi][nj][3] + bias_s[colrel + 1];
            #pragma unroll
            for (int rr = 0; rr < 2; rr++) {
                int row = m0 + core.m0w + mi * 16 + g + rr * 8;
                int bb_ = row >> 11, sidx = row & 2047;
                int drow = sidx;
                bool store = true;
                if (compact) {
                    store = (mask[bb_ * SS + sidx] != 0);
                    drow  = pos[bb_ * SS + sidx];
                }
                if (store) {
                    size_t dst = ((size_t)(bb_ * NH + hh) * SS + drow) * DH + dh;
                    uint32_t hp, lp;
                    if (rr == 0) split_pack(c0, c1, hp, lp);
                    else         split_pack(c2, c3, hp, lp);
                    *reinterpret_cast<uint32_t*>(H + dst) = hp;
                    *reinterpret_cast<uint32_t*>(L + dst) = lp;
                }
            }
        }
    }
}

// ---------------------------------------------------------------------------
// Output projection GEMM: fp32 out
// ---------------------------------------------------------------------------
__global__ void __launch_bounds__(128, 2)
gemm_out(const __nv_bfloat16* __restrict__ A3, const __nv_bfloat16* __restrict__ W3,
         const float* __restrict__ bias, float* __restrict__ C)
{
    extern __shared__ char smem[];
    const uint32_t sb = smem_u32(smem);
    const int tid = threadIdx.x, wid = tid >> 5, lid = tid & 31;
    const int m0 = blockIdx.y * 128, n0 = blockIdx.x * 128;

    float* bias_s = (float*)smem;
    if (tid < 128) bias_s[tid] = bias[n0 + tid];

    GemmCore core;
    core.run(sb, tid, wid, lid, A3 + (size_t)m0 * KW, W3 + (size_t)n0 * KW);

    const int g = lid >> 2, t = lid & 3;
    #pragma unroll
    for (int mi = 0; mi < 4; mi++) {
        #pragma unroll
        for (int nj = 0; nj < 8; nj++) {
            int colrel = core.n0w + nj * 8 + 2 * t;
            int col = n0 + colrel;
            int row0 = m0 + core.m0w + mi * 16 + g;
            float2 v0 = {core.acc[mi][nj][0] + bias_s[colrel],
                         core.acc[mi][nj][1] + bias_s[colrel + 1]};
            float2 v1 = {core.acc[mi][nj][2] + bias_s[colrel],
                         core.acc[mi][nj][3] + bias_s[colrel + 1]};
            *reinterpret_cast<float2*>(C + (size_t)row0 * DF + col) = v0;
            *reinterpret_cast<float2*>(C + (size_t)(row0 + 8) * DF + col) = v1;
        }
    }
}

// ---------------------------------------------------------------------------
// FlashAttention-2 on mma.sync over COMPACTED keys (exact: masked keys
// contribute exactly 0). Tail tile masked by index >= cnt.
// ---------------------------------------------------------------------------
__global__ void __launch_bounds__(256, 1)
attn_mma(const __nv_bfloat16* __restrict__ Qh_, const __nv_bfloat16* __restrict__ Ql_,
         const __nv_bfloat16* __restrict__ Kh_, const __nv_bfloat16* __restrict__ Kl_,
         const __nv_bfloat16* __restrict__ Vh_, const __nv_bfloat16* __restrict__ Vl_,
         const int* __restrict__ cnt_, __nv_bfloat16* __restrict__ A3out)
{
    extern __shared__ char smem[];
    const uint32_t sb = smem_u32(smem);
    const int tid = threadIdx.x, wid = tid >> 5, lid = tid & 31;
    const int g = lid >> 2, t4 = lid & 3;
    const int b = blockIdx.z, h = blockIdx.y;
    const int bh = b * NH + h;
    const int q0 = blockIdx.x * 128;
    const int m0w = wid * 16;
    const float SC = 0.03125f;

    const int cnt = cnt_[b];
    const int nt = (cnt + 63) >> 6;

    // ---- stage Q (hi,lo) through smem into register a-frags ----
    {
        const size_t qbase = ((size_t)bh * SS + q0);
        #pragma unroll
        for (int i = 0; i < 4; i++) {
            int seg = i * 256 + tid;
            int row = seg >> 3, cs = seg & 7;
            const size_t src = (qbase + row) * DH + cs * 8;
            uint32_t d = sb + (uint32_t)(row * PITCHB + cs * 16);
            cp_async_16(d,          Qh_ + src);
            cp_async_16(d + QL_OFF, Ql_ + src);
        }
    }
    CP_COMMIT(); CP_WAIT0(); __syncthreads();

    uint32_t qh[4][4], ql[4][4];
    #pragma unroll
    for (int kk = 0; kk < 4; kk++) {
        uint32_t a = sb + (uint32_t)((m0w + (lid & 15)) * PITCHB + kk * 32 + ((lid >> 4) << 4));
        ldsm_x4(qh[kk][0], qh[kk][1], qh[kk][2], qh[kk][3], a);
        ldsm_x4(ql[kk][0], ql[kk][1], ql[kk][2], ql[kk][3], a + QL_OFF);
    }
    __syncthreads();

    auto load_tile = [&](int ti, int st) {
        const uint32_t stage = sb + st * ASTRIDE;
        const size_t kbase = ((size_t)bh * SS + ti * 64);
        #pragma unroll
        for (int i = 0; i < 2; i++) {
            int seg = i * 256 + tid;
            int row = seg >> 3, cs = seg & 7;
            size_t src = (kbase + row) * DH + cs * 8;
            uint32_t d = stage + (uint32_t)(row * PITCHB + cs * 16);
            cp_async_16(d,             Kh_ + src);
            cp_async_16(d + ATILE,     Kl_ + src);
            cp_async_16(d + 2 * ATILE, Vh_ + src);
            cp_async_16(d + 3 * ATILE, Vl_ + src);
        }
    };

    float m0 = -1e30f, m1 = -1e30f, l0 = 0.f, l1 = 0.f;
    float o[8][4];
    #pragma unroll
    for (int nj = 0; nj < 8; nj++)
        #pragma unroll
        for (int e = 0; e < 4; e++) o[nj][e] = 0.f;

    if (0 < nt) load_tile(0, 0);
    CP_COMMIT();
    if (1 < nt) load_tile(1, 1);
    CP_COMMIT();

    for (int ti = 0; ti < nt; ti++) {
        const int st = ti % 3;
        CP_WAIT1();
        __syncthreads();
        if (ti + 2 < nt) load_tile(ti + 2, (ti + 2) % 3);
        CP_COMMIT();

        const uint32_t sK  = sb + st * ASTRIDE;
        const uint32_t sKl = sK + ATILE, sV = sK + 2 * ATILE, sVl = sK + 3 * ATILE;

        // ---- S = Qh Kh^T + Ql Kh^T + Qh Kl^T ----
        float s[8][4];
        #pragma unroll
        for (int nj = 0; nj < 8; nj++)
            #pragma unroll
            for (int e = 0; e < 4; e++) s[nj][e] = 0.f;

        #pragma unroll
        for (int kk = 0; kk < 4; kk++) {
            uint32_t kb[4][4];
            #pragma unroll
            for (int ni = 0; ni < 4; ni++) {
                uint32_t a = sK + (uint32_t)((ni * 16 + (lid & 7) + ((lid >> 4) & 1) * 8) * PITCHB
                             + kk * 32 + (((lid >> 3) & 1) << 4));
                ldsm_x4(kb[ni][0], kb[ni][1], kb[ni][2], kb[ni][3], a);
            }
            #pragma unroll
            for (int nj = 0; nj < 8; nj++) mma16816(s[nj], qh[kk], &kb[nj >> 1][(nj & 1) * 2]);
            #pragma unroll
            for (int nj = 0; nj < 8; nj++) mma16816(s[nj], ql[kk], &kb[nj >> 1][(nj & 1) * 2]);
            #pragma unroll
            for (int ni = 0; ni < 4; ni++) {
                uint32_t a = sKl + (uint32_t)((ni * 16 + (lid & 7) + ((lid >> 4) & 1) * 8) * PITCHB
                             + kk * 32 + (((lid >> 3) & 1) << 4));
                ldsm_x4(kb[ni][0], kb[ni][1], kb[ni][2], kb[ni][3], a);
            }
            #pragma unroll
            for (int nj = 0; nj < 8; nj++) mma16816(s[nj], qh[kk], &kb[nj >> 1][(nj & 1) * 2]);
        }

        // ---- scale + tail mask + online softmax ----
        const int kbase_idx = ti * 64;
        float tmax0 = -1e30f, tmax1 = -1e30f;
        #pragma unroll
        for (int nj = 0; nj < 8; nj++) {
            int k0i = kbase_idx + nj * 8 + 2 * t4;
            bool v0 = k0i < cnt, v1 = (k0i + 1) < cnt;
            float s0 = v0 ? s[nj][0] * SC : -1e9f;
            float s1 = v1 ? s[nj][1] * SC : -1e9f;
            float s2 = v0 ? s[nj][2] * SC : -1e9f;
            float s3 = v1 ? s[nj][3] * SC : -1e9f;
            s[nj][0] = s0; s[nj][1] = s1; s[nj][2] = s2; s[nj][3] = s3;
            tmax0 = fmaxf(tmax0, fmaxf(s0, s1));
            tmax1 = fmaxf(tmax1, fmaxf(s2, s3));
        }
        tmax0 = fmaxf(tmax0, __shfl_xor_sync(0xffffffffu, tmax0, 1));
        tmax0 = fmaxf(tmax0, __shfl_xor_sync(0xffffffffu, tmax0, 2));
        tmax1 = fmaxf(tmax1, __shfl_xor_sync(0xffffffffu, tmax1, 1));
        tmax1 = fmaxf(tmax1, __shfl_xor_sync(0xffffffffu, tmax1, 2));

        float mn0 = fmaxf(m0, tmax0), mn1 = fmaxf(m1, tmax1);
        float sc0 = __expf(m0 - mn0), sc1 = __expf(m1 - mn1);
        m0 = mn0; m1 = mn1;
        l0 *= sc0; l1 *= sc1;
        #pragma unroll
        for (int nj = 0; nj < 8; nj++) {
            o[nj][0] *= sc0; o[nj][1] *= sc0;
            o[nj][2] *= sc1; o[nj][3] *= sc1;
        }
        #pragma unroll
        for (int nj = 0; nj < 8; nj++) {
            float p0 = __expf(s[nj][0] - m0);
            float p1 = __expf(s[nj][1] - m0);
            float p2 = __expf(s[nj][2] - m1);
            float p3 = __expf(s[nj][3] - m1);
            s[nj][0] = p0; s[nj][1] = p1; s[nj][2] = p2; s[nj][3] = p3;
            l0 += p0 + p1; l1 += p2 + p3;
        }

        // ---- O += Ph Vh + Pl Vh + Ph Vl ----
        #pragma unroll
        for (int kk = 0; kk < 4; kk++) {
            uint32_t ah[4], al[4];
            split_pack(s[2 * kk][0],     s[2 * kk][1],     ah[0], al[0]);
            split_pack(s[2 * kk][2],     s[2 * kk][3],     ah[1], al[1]);
            split_pack(s[2 * kk + 1][0], s[2 * kk + 1][1], ah[2], al[2]);
            split_pack(s[2 * kk + 1][2], s[2 * kk + 1][3], ah[3], al[3]);

            uint32_t vb[4][4];
            #pragma unroll
            for (int njp = 0; njp < 4; njp++) {
                uint32_t a = sV + (uint32_t)((16 * kk + (lid & 7) + ((lid >> 3) & 1) * 8) * PITCHB
                             + (16 * njp + ((lid >> 4) & 1) * 8) * 2);
                ldsm_x4_t(vb[njp][0], vb[njp][1], vb[njp][2], vb[njp][3], a);
            }
            #pragma unroll
            for (int nj = 0; nj < 8; nj++) mma16816(o[nj], ah, &vb[nj >> 1][(nj & 1) * 2]);
            #pragma unroll
            for (int nj = 0; nj < 8; nj++) mma16816(o[nj], al, &vb[nj >> 1][(nj & 1) * 2]);
            #pragma unroll
            for (int njp = 0; njp < 4; njp++) {
                uint32_t a = sVl + (uint32_t)((16 * kk + (lid & 7) + ((lid >> 3) & 1) * 8) * PITCHB
                             + (16 * njp + ((lid >> 4) & 1) * 8) * 2);
                ldsm_x4_t(vb[njp][0], vb[njp][1], vb[njp][2], vb[njp][3], a);
            }
            #pragma unroll
            for (int nj = 0; nj < 8; nj++) mma16816(o[nj], ah, &vb[nj >> 1][(nj & 1) * 2]);
        }
        __syncthreads();
    }
    CP_WAIT0();

    // ---- finalize + write split bf16 straight into A3 [hi|lo|hi] ----
    l0 += __shfl_xor_sync(0xffffffffu, l0, 1);
    l0 += __shfl_xor_sync(0xffffffffu, l0, 2);
    l1 += __shfl_xor_sync(0xffffffffu, l1, 1);
    l1 += __shfl_xor_sync(0xffffffffu, l1, 2);
    float inv0 = 1.f / l0, inv1 = 1.f / l1;

    const int srow = q0 + m0w + g;
    size_t r0 = (size_t)(b * SS + srow) * KW;
    size_t r1 = r0 + (size_t)8 * KW;
    const int colbase = h * DH;

    #pragma unroll
    for (int nj = 0; nj < 8; nj++) {
        int c = colbase + nj * 8 + 2 * t4;
        uint32_t hp, lp;
        split_pack(o[nj][0] * inv0, o[nj][1] * inv0, hp, lp);
        *reinterpret_cast<uint32_t*>(A3out + r0 + c)        = hp;
        *reinterpret_cast<uint32_t*>(A3out + r0 + 1024 + c) = lp;
        *reinterpret_cast<uint32_t*>(A3out + r0 + 2048 + c) = hp;
        split_pack(o[nj][2] * inv1, o[nj][3] * inv1, hp, lp);
        *reinterpret_cast<uint32_t*>(A3out + r1 + c)        = hp;
        *reinterpret_cast<uint32_t*>(A3out + r1 + 1024 + c) = lp;
        *reinterpret_cast<uint32_t*>(A3out + r1 + 2048 + c) = hp;
    }
}

// ---------------------------------------------------------------------------
// launch
// ---------------------------------------------------------------------------
extern "C" void kernel_launch(void* const* d_in, const int* in_sizes, int n_in,
                              void* d_out, int out_size)
{
    const float* Q    = (const float*)d_in[0];
    const float* K    = (const float*)d_in[1];
    const float* V    = (const float*)d_in[2];
    const int*   mask = (const int*)  d_in[3];
    const float* Wq   = (const float*)d_in[4];
    const float* bq   = (const float*)d_in[5];
    const float* Wk   = (const float*)d_in[6];
    const float* bk   = (const float*)d_in[7];
    const float* Wv   = (const float*)d_in[8];
    const float* bv   = (const float*)d_in[9];
    const float* Wo   = (const float*)d_in[10];
    const float* bo   = (const float*)d_in[11];
    float* out = (float*)d_out;

    __nv_bfloat16 *A3, *W3, *Qh, *Ql, *Kh, *Kl, *Vh, *Vl;
    int *pos, *cnt;
    cudaGetSymbolAddress((void**)&A3, g_A3v3);
    cudaGetSymbolAddress((void**)&W3, g_W3v4);
    cudaGetSymbolAddress((void**)&Qh, g_Qh);
    cudaGetSymbolAddress((void**)&Ql, g_Ql);
    cudaGetSymbolAddress((void**)&Kh, g_Kh);
    cudaGetSymbolAddress((void**)&Kl, g_Kl);
    cudaGetSymbolAddress((void**)&Vh, g_Vh);
    cudaGetSymbolAddress((void**)&Vl, g_Vl);
    cudaGetSymbolAddress((void**)&pos, g_pos);
    cudaGetSymbolAddress((void**)&cnt, g_cnt);

    cudaFuncSetAttribute(gemm_qkv, cudaFuncAttributeMaxDynamicSharedMemorySize, GEMM_SMEM);
    cudaFuncSetAttribute(gemm_out, cudaFuncAttributeMaxDynamicSharedMemorySize, GEMM_SMEM);
    cudaFuncSetAttribute(attn_mma, cudaFuncAttributeMaxDynamicSharedMemorySize, ATTN_SMEM);

    mask_scan<<<BB, 256>>>(mask, pos, cnt);
    conv_w<<<dim3(DF * DF / 1024, 4), 256>>>(Wq, Wk, Wv, Wo, W3);
    conv_in<<<dim3(MROWS * DF / 1024, 3), 256>>>(Q, K, V, A3);

    gemm_qkv<<<dim3(DF / 128, MROWS / 128, 3), 128, GEMM_SMEM>>>(
        A3, W3, bq, bk, bv, mask, pos, Qh, Ql, Kh, Kl, Vh, Vl);

    zero_tail<<<dim3(BB, NH), 256>>>(cnt, Kh, Kl, Vh, Vl);

    attn_mma<<<dim3(SS / 128, NH, BB), 256, ATTN_SMEM>>>(Qh, Ql, Kh, Kl, Vh, Vl, cnt, A3);

    gemm_out<<<dim3(DF / 128, MROWS / 128), 128, GEMM_SMEM>>>(
        A3, W3 + (size_t)3 * DF * KW, bo, out);
}